// round 1
// baseline (speedup 1.0000x reference)
#include <cuda_runtime.h>

#define K_COMP   8
#define L_LAT    64
#define D_DATA   256
#define N_ROWS   16384
#define B_ROWS   2048
#define ENC_OUT  1536   // 3*K*L
#define DEC_OUT  6144   // 3*K*D
#define NB_SAMP  4096   // (16384*64)/256
#define NB_DEC   512    // 16384/32

__device__ float g_pred_e[B_ROWS * ENC_OUT];   // 12.6 MB
__device__ float g_h[N_ROWS * L_LAT];          // 4 MB
__device__ float g_partB[NB_SAMP];
__device__ float g_partC[NB_DEC];

__device__ __forceinline__ float block_reduce_256(float v) {
    __shared__ float red[8];
    int lane = threadIdx.x & 31, wid = threadIdx.x >> 5;
    #pragma unroll
    for (int o = 16; o > 0; o >>= 1) v += __shfl_down_sync(0xffffffffu, v, o);
    if (lane == 0) red[wid] = v;
    __syncthreads();
    if (wid == 0) {
        v = (lane < 8) ? red[lane] : 0.0f;
        #pragma unroll
        for (int o = 4; o > 0; o >>= 1) v += __shfl_down_sync(0xffffffffu, v, o);
    }
    return v;   // valid on thread 0
}

// ---------------------------------------------------------------------------
// Encoder GEMM: pred_e(2048,1536) = x(2048,256) @ W_e(256,1536) + b_e
// 64x64 block tile, 256 threads, 4x4 register tile, K-step 16.
// ---------------------------------------------------------------------------
__global__ __launch_bounds__(256) void enc_gemm(const float* __restrict__ x,
                                                const float* __restrict__ We,
                                                const float* __restrict__ be)
{
    __shared__ float As[16][64];
    __shared__ float Bs[16][64];
    const int tid = threadIdx.x;
    const int tx = tid & 15, ty = tid >> 4;
    const int bm = blockIdx.y * 64, bn = blockIdx.x * 64;

    float acc[4][4];
    #pragma unroll
    for (int i = 0; i < 4; i++)
        #pragma unroll
        for (int j = 0; j < 4; j++) acc[i][j] = 0.0f;

    const int am = tid >> 2;          // 0..63
    const int ak = (tid & 3) * 4;     // 0,4,8,12
    const int bk = tid >> 6;          // 0..3
    const int bnn = tid & 63;

    for (int kt = 0; kt < 256; kt += 16) {
        // load A tile (transposed into As[k][m])
        float4 xa = *reinterpret_cast<const float4*>(x + (bm + am) * D_DATA + kt + ak);
        As[ak + 0][am] = xa.x;
        As[ak + 1][am] = xa.y;
        As[ak + 2][am] = xa.z;
        As[ak + 3][am] = xa.w;
        // load B tile
        #pragma unroll
        for (int i = 0; i < 4; i++)
            Bs[bk + i * 4][bnn] = We[(kt + bk + i * 4) * ENC_OUT + bn + bnn];
        __syncthreads();

        #pragma unroll
        for (int kk = 0; kk < 16; kk++) {
            float4 av = *reinterpret_cast<const float4*>(&As[kk][ty * 4]);
            float4 bv = *reinterpret_cast<const float4*>(&Bs[kk][tx * 4]);
            float a0 = av.x, a1 = av.y, a2 = av.z, a3 = av.w;
            float b0 = bv.x, b1 = bv.y, b2 = bv.z, b3 = bv.w;
            acc[0][0] += a0 * b0; acc[0][1] += a0 * b1; acc[0][2] += a0 * b2; acc[0][3] += a0 * b3;
            acc[1][0] += a1 * b0; acc[1][1] += a1 * b1; acc[1][2] += a1 * b2; acc[1][3] += a1 * b3;
            acc[2][0] += a2 * b0; acc[2][1] += a2 * b1; acc[2][2] += a2 * b2; acc[2][3] += a2 * b3;
            acc[3][0] += a3 * b0; acc[3][1] += a3 * b1; acc[3][2] += a3 * b2; acc[3][3] += a3 * b3;
        }
        __syncthreads();
    }

    #pragma unroll
    for (int i = 0; i < 4; i++) {
        #pragma unroll
        for (int j = 0; j < 4; j++) {
            int col = bn + tx * 4 + j;
            g_pred_e[(bm + ty * 4 + i) * ENC_OUT + col] = acc[i][j] + be[col];
        }
    }
}

// ---------------------------------------------------------------------------
// Sampling + h + (L_q - L_e) partials. One thread per (n, l).
// pred_e row layout: m at [k*64+l], logp at [512+k*64+l], loga at [1024+k*64+l]
// ---------------------------------------------------------------------------
__global__ __launch_bounds__(256) void sample_k(const float* __restrict__ ue,
                                                const float* __restrict__ rr)
{
    const int g = blockIdx.x * 256 + threadIdx.x;
    const int n = g >> 6, l = g & 63;
    const float* row = g_pred_e + (n & (B_ROWS - 1)) * ENC_OUT;

    float a[K_COMP], e[K_COMP];
    float amax = -1e30f;
    #pragma unroll
    for (int k = 0; k < K_COMP; k++) {
        a[k] = row[1024 + k * 64 + l];
        amax = fmaxf(amax, a[k]);
    }
    float s = 0.0f;
    #pragma unroll
    for (int k = 0; k < K_COMP; k++) { e[k] = __expf(a[k] - amax); s += e[k]; }
    const float lse_a = amax + __logf(s);
    const float inv = 1.0f / s;

    const float rv = rr[n * 64 + l];
    float c = 0.0f;
    int idx = 0;
    #pragma unroll
    for (int k = 0; k < K_COMP; k++) {
        c += e[k] * inv;
        idx += (rv > c) ? 1 : 0;
    }
    if (idx > K_COMP - 1) idx = K_COMP - 1;

    const float msel = row[idx * 64 + l];
    const float psel = row[512 + idx * 64 + l];
    const float hv = msel + __expf(-0.5f * psel) * ue[n * 64 + l];
    g_h[n * 64 + l] = hv;

    float st = 0.0f;
    #pragma unroll
    for (int k = 0; k < K_COMP; k++) {
        float m = row[k * 64 + l];
        float p = row[512 + k * 64 + l];
        float dd = hv - m;
        st += __expf(a[k] + 0.5f * p - 0.5f * __expf(p) * dd * dd);
    }
    const float lse_s = __logf(st) - lse_a;      // logsumexp_k of (loga_norm + 0.5p - 0.5 uh^2)

    float v = -0.5f * hv * hv - lse_s;           // (L_q - L_e) per-(n,l), constants cancel
    v = block_reduce_256(v);
    if (threadIdx.x == 0) g_partB[blockIdx.x] = v;
}

// ---------------------------------------------------------------------------
// Fused decoder GEMM + mixture likelihood.
// Block: 256 threads (1 thread per d-column), 32 rows per block, 4 groups of 8
// rows register-tiled. W_d (64,6144) streamed from L2, reused across 8 rows.
// pred_d col layout: m at k*256+d, logp at 2048+k*256+d, loga at 4096+k*256+d.
// ---------------------------------------------------------------------------
__global__ __launch_bounds__(256, 2) void dec_k(const float* __restrict__ x,
                                                const float* __restrict__ Wd,
                                                const float* __restrict__ bd)
{
    const int d = threadIdx.x;
    const int row0 = blockIdx.x * 32;
    __shared__ float hs[8][64];

    float part = 0.0f;

    for (int gp = 0; gp < 4; gp++) {
        const int rbase = row0 + gp * 8;
        __syncthreads();
        {
            int i = threadIdx.x;
            hs[i >> 6][i & 63] = g_h[(rbase + (i >> 6)) * 64 + (i & 63)];
            i += 256;
            hs[i >> 6][i & 63] = g_h[(rbase + (i >> 6)) * 64 + (i & 63)];
        }
        __syncthreads();

        float xv[8];
        #pragma unroll
        for (int r = 0; r < 8; r++)
            xv[r] = x[((rbase + r) & (B_ROWS - 1)) * D_DATA + d];

        float sum_t[8], sum_a[8];
        #pragma unroll
        for (int r = 0; r < 8; r++) { sum_t[r] = 0.0f; sum_a[r] = 0.0f; }

        for (int k = 0; k < K_COMP; k++) {
            float am[8], ap[8], aa[8];
            #pragma unroll
            for (int r = 0; r < 8; r++) { am[r] = 0.0f; ap[r] = 0.0f; aa[r] = 0.0f; }

            const float* wbase = Wd + k * D_DATA + d;
            #pragma unroll 4
            for (int l4 = 0; l4 < 16; l4++) {
                const float* wl = wbase + l4 * 4 * DEC_OUT;
                float wm0 = wl[0 * DEC_OUT], wm1 = wl[1 * DEC_OUT],
                      wm2 = wl[2 * DEC_OUT], wm3 = wl[3 * DEC_OUT];
                float wp0 = wl[0 * DEC_OUT + 2048], wp1 = wl[1 * DEC_OUT + 2048],
                      wp2 = wl[2 * DEC_OUT + 2048], wp3 = wl[3 * DEC_OUT + 2048];
                float wa0 = wl[0 * DEC_OUT + 4096], wa1 = wl[1 * DEC_OUT + 4096],
                      wa2 = wl[2 * DEC_OUT + 4096], wa3 = wl[3 * DEC_OUT + 4096];
                #pragma unroll
                for (int r = 0; r < 8; r++) {
                    float4 hv = *reinterpret_cast<const float4*>(&hs[r][l4 * 4]);
                    am[r] += hv.x * wm0 + hv.y * wm1 + hv.z * wm2 + hv.w * wm3;
                    ap[r] += hv.x * wp0 + hv.y * wp1 + hv.z * wp2 + hv.w * wp3;
                    aa[r] += hv.x * wa0 + hv.y * wa1 + hv.z * wa2 + hv.w * wa3;
                }
            }
            const float bm = bd[k * D_DATA + d];
            const float bp = bd[2048 + k * D_DATA + d];
            const float ba = bd[4096 + k * D_DATA + d];
            #pragma unroll
            for (int r = 0; r < 8; r++) {
                float m = am[r] + bm;
                float p = ap[r] + bp;
                float av = aa[r] + ba;
                float dd = xv[r] - m;
                float t = av + 0.5f * p - 0.5f * __expf(p) * dd * dd;
                sum_t[r] += __expf(t);
                sum_a[r] += __expf(av);
            }
        }
        #pragma unroll
        for (int r = 0; r < 8; r++)
            part += __logf(sum_t[r]) - __logf(sum_a[r]);
    }

    __syncthreads();
    part = block_reduce_256(part);
    if (threadIdx.x == 0) g_partC[blockIdx.x] = part;
}

// ---------------------------------------------------------------------------
// Final reduction: out = -( (PB + PC)/N + c2 ),  c2 = -0.5*D*log(2*pi)
// ---------------------------------------------------------------------------
__global__ __launch_bounds__(256) void final_k(float* __restrict__ out)
{
    float s = 0.0f;
    for (int i = threadIdx.x; i < NB_SAMP; i += 256) s += g_partB[i];
    for (int i = threadIdx.x; i < NB_DEC; i += 256) s += g_partC[i];
    s = block_reduce_256(s);
    if (threadIdx.x == 0) {
        const float c2 = -0.5f * 256.0f * 1.8378770664093453f;
        out[0] = -(s / (float)N_ROWS + c2);
    }
}

extern "C" void kernel_launch(void* const* d_in, const int* in_sizes, int n_in,
                              void* d_out, int out_size) {
    const float* x  = (const float*)d_in[0];
    const float* We = (const float*)d_in[1];
    const float* be = (const float*)d_in[2];
    const float* Wd = (const float*)d_in[3];
    const float* bd = (const float*)d_in[4];
    const float* ue = (const float*)d_in[5];
    const float* rr = (const float*)d_in[6];
    float* out = (float*)d_out;

    dim3 ge(ENC_OUT / 64, B_ROWS / 64);
    enc_gemm<<<ge, 256>>>(x, We, be);
    sample_k<<<NB_SAMP, 256>>>(ue, rr);
    dec_k<<<NB_DEC, 256>>>(x, Wd, bd);
    final_k<<<1, 256>>>(out);
}

// round 2
// speedup vs baseline: 1.3979x; 1.3979x over previous
#include <cuda_runtime.h>

#define K_COMP   8
#define L_LAT    64
#define D_DATA   256
#define N_ROWS   16384
#define B_ROWS   2048
#define ENC_OUT  1536   // 3*K*L
#define DEC_OUT  6144   // 3*K*D
#define NB_SAMP  4096   // (16384*64)/256
#define ROWS_PB  16
#define NB_DEC   (N_ROWS / ROWS_PB)   // 1024

__device__ float g_pred_e[B_ROWS * ENC_OUT];   // 12.6 MB
__device__ float g_h[N_ROWS * L_LAT];          // 4 MB
__device__ float g_partB[NB_SAMP];
__device__ float g_partC[NB_DEC];

// ---- packed f32x2 helpers ------------------------------------------------
typedef unsigned long long u64;

__device__ __forceinline__ u64 pack2(float lo, float hi) {
    u64 o; asm("mov.b64 %0, {%1, %2};" : "=l"(o) : "f"(lo), "f"(hi)); return o;
}
__device__ __forceinline__ u64 bcast2(float v) {
    u64 o; asm("mov.b64 %0, {%1, %1};" : "=l"(o) : "f"(v)); return o;
}
__device__ __forceinline__ void unpack2(u64 d, float& lo, float& hi) {
    asm("mov.b64 {%0, %1}, %2;" : "=f"(lo), "=f"(hi) : "l"(d));
}
__device__ __forceinline__ void fma2(u64& d, u64 a, u64 b) {
    asm("fma.rn.f32x2 %0, %1, %2, %0;" : "+l"(d) : "l"(a), "l"(b));
}

__device__ __forceinline__ float block_reduce_256(float v) {
    __shared__ float red[8];
    int lane = threadIdx.x & 31, wid = threadIdx.x >> 5;
    #pragma unroll
    for (int o = 16; o > 0; o >>= 1) v += __shfl_down_sync(0xffffffffu, v, o);
    if (lane == 0) red[wid] = v;
    __syncthreads();
    if (wid == 0) {
        v = (lane < 8) ? red[lane] : 0.0f;
        #pragma unroll
        for (int o = 4; o > 0; o >>= 1) v += __shfl_down_sync(0xffffffffu, v, o);
    }
    return v;   // valid on thread 0
}

// ---------------------------------------------------------------------------
// Encoder GEMM: pred_e(2048,1536) = x(2048,256) @ W_e(256,1536) + b_e
// 64x64 block tile, 256 threads, 4x4 register tile (j packed f32x2), K-step 16.
// ---------------------------------------------------------------------------
__global__ __launch_bounds__(256) void enc_gemm(const float* __restrict__ x,
                                                const float* __restrict__ We,
                                                const float* __restrict__ be)
{
    __shared__ float As[16][64];
    __shared__ float Bs[16][64];
    const int tid = threadIdx.x;
    const int tx = tid & 15, ty = tid >> 4;
    const int bm = blockIdx.y * 64, bn = blockIdx.x * 64;

    u64 acc[4][2];
    #pragma unroll
    for (int i = 0; i < 4; i++) { acc[i][0] = pack2(0.f, 0.f); acc[i][1] = pack2(0.f, 0.f); }

    const int am = tid >> 2;          // 0..63
    const int ak = (tid & 3) * 4;     // 0,4,8,12
    const int bk = tid >> 6;          // 0..3
    const int bnn = tid & 63;

    for (int kt = 0; kt < 256; kt += 16) {
        float4 xa = *reinterpret_cast<const float4*>(x + (bm + am) * D_DATA + kt + ak);
        As[ak + 0][am] = xa.x;
        As[ak + 1][am] = xa.y;
        As[ak + 2][am] = xa.z;
        As[ak + 3][am] = xa.w;
        #pragma unroll
        for (int i = 0; i < 4; i++)
            Bs[bk + i * 4][bnn] = We[(kt + bk + i * 4) * ENC_OUT + bn + bnn];
        __syncthreads();

        #pragma unroll
        for (int kk = 0; kk < 16; kk++) {
            float4 av = *reinterpret_cast<const float4*>(&As[kk][ty * 4]);
            u64 b01 = *reinterpret_cast<const u64*>(&Bs[kk][tx * 4]);
            u64 b23 = *reinterpret_cast<const u64*>(&Bs[kk][tx * 4 + 2]);
            u64 a0 = bcast2(av.x), a1 = bcast2(av.y), a2 = bcast2(av.z), a3 = bcast2(av.w);
            fma2(acc[0][0], a0, b01); fma2(acc[0][1], a0, b23);
            fma2(acc[1][0], a1, b01); fma2(acc[1][1], a1, b23);
            fma2(acc[2][0], a2, b01); fma2(acc[2][1], a2, b23);
            fma2(acc[3][0], a3, b01); fma2(acc[3][1], a3, b23);
        }
        __syncthreads();
    }

    #pragma unroll
    for (int i = 0; i < 4; i++) {
        float v0, v1, v2, v3;
        unpack2(acc[i][0], v0, v1);
        unpack2(acc[i][1], v2, v3);
        int col = bn + tx * 4;
        float* outp = g_pred_e + (bm + ty * 4 + i) * ENC_OUT + col;
        outp[0] = v0 + be[col + 0];
        outp[1] = v1 + be[col + 1];
        outp[2] = v2 + be[col + 2];
        outp[3] = v3 + be[col + 3];
    }
}

// ---------------------------------------------------------------------------
// Sampling + h + (L_q - L_e) partials. One thread per (n, l).
// ---------------------------------------------------------------------------
__global__ __launch_bounds__(256) void sample_k(const float* __restrict__ ue,
                                                const float* __restrict__ rr)
{
    const int g = blockIdx.x * 256 + threadIdx.x;
    const int n = g >> 6, l = g & 63;
    const float* row = g_pred_e + (n & (B_ROWS - 1)) * ENC_OUT;

    float a[K_COMP], e[K_COMP];
    float amax = -1e30f;
    #pragma unroll
    for (int k = 0; k < K_COMP; k++) {
        a[k] = row[1024 + k * 64 + l];
        amax = fmaxf(amax, a[k]);
    }
    float s = 0.0f;
    #pragma unroll
    for (int k = 0; k < K_COMP; k++) { e[k] = __expf(a[k] - amax); s += e[k]; }
    const float lse_a = amax + __logf(s);
    const float inv = 1.0f / s;

    const float rv = rr[n * 64 + l];
    float c = 0.0f;
    int idx = 0;
    #pragma unroll
    for (int k = 0; k < K_COMP; k++) {
        c += e[k] * inv;
        idx += (rv > c) ? 1 : 0;
    }
    if (idx > K_COMP - 1) idx = K_COMP - 1;

    const float msel = row[idx * 64 + l];
    const float psel = row[512 + idx * 64 + l];
    const float hv = msel + __expf(-0.5f * psel) * ue[n * 64 + l];
    g_h[n * 64 + l] = hv;

    float st = 0.0f;
    #pragma unroll
    for (int k = 0; k < K_COMP; k++) {
        float m = row[k * 64 + l];
        float p = row[512 + k * 64 + l];
        float dd = hv - m;
        st += __expf(a[k] + 0.5f * p - 0.5f * __expf(p) * dd * dd);
    }
    const float lse_s = __logf(st) - lse_a;

    float v = -0.5f * hv * hv - lse_s;
    v = block_reduce_256(v);
    if (threadIdx.x == 0) g_partB[blockIdx.x] = v;
}

// ---------------------------------------------------------------------------
// Fused decoder GEMM + mixture likelihood (packed f32x2 over row pairs).
// Block: 256 threads (1 thread per d-column), 16 rows per block = 8 row pairs.
// W_d streamed from L2 (1.57MB, fully resident), h pairs broadcast from smem.
// ---------------------------------------------------------------------------
__global__ __launch_bounds__(256, 2) void dec_k(const float* __restrict__ x,
                                                const float* __restrict__ Wd,
                                                const float* __restrict__ bd)
{
    const int d = threadIdx.x;
    const int row0 = blockIdx.x * ROWS_PB;
    __shared__ float2 hp[64][8];   // [l][pair]: (h[2p][l], h[2p+1][l])

    {
        int i = threadIdx.x;
        #pragma unroll
        for (int t = 0; t < 4; t++, i += 256) {
            int r = i >> 6, l = i & 63;
            float v = g_h[(row0 + r) * 64 + l];
            reinterpret_cast<float*>(&hp[l][r >> 1])[r & 1] = v;
        }
    }
    __syncthreads();

    float xv[ROWS_PB];
    const int xrow = row0 & (B_ROWS - 1);   // row0 multiple of 16, no wrap within group
    #pragma unroll
    for (int r = 0; r < ROWS_PB; r++)
        xv[r] = x[(xrow + r) * D_DATA + d];

    float sum_t[ROWS_PB], sum_a[ROWS_PB];
    #pragma unroll
    for (int r = 0; r < ROWS_PB; r++) { sum_t[r] = 0.0f; sum_a[r] = 0.0f; }

    for (int k = 0; k < K_COMP; k++) {
        u64 am[8], ap[8], aa[8];
        #pragma unroll
        for (int p = 0; p < 8; p++) {
            am[p] = pack2(0.f, 0.f); ap[p] = pack2(0.f, 0.f); aa[p] = pack2(0.f, 0.f);
        }

        const float* w = Wd + k * D_DATA + d;
        #pragma unroll 4
        for (int l = 0; l < 64; l++) {
            const float* wl = w + l * DEC_OUT;
            u64 wm = bcast2(wl[0]);
            u64 wp = bcast2(wl[2048]);
            u64 wa = bcast2(wl[4096]);
            #pragma unroll
            for (int p = 0; p < 8; p++) {
                u64 hv = *reinterpret_cast<const u64*>(&hp[l][p]);
                fma2(am[p], hv, wm);
                fma2(ap[p], hv, wp);
                fma2(aa[p], hv, wa);
            }
        }

        const float bm = bd[k * D_DATA + d];
        const float bp = bd[2048 + k * D_DATA + d];
        const float ba = bd[4096 + k * D_DATA + d];
        #pragma unroll
        for (int p = 0; p < 8; p++) {
            float m0, m1, p0, p1, g0, g1;
            unpack2(am[p], m0, m1);
            unpack2(ap[p], p0, p1);
            unpack2(aa[p], g0, g1);
            {
                float m = m0 + bm, pv = p0 + bp, av = g0 + ba;
                float dd = xv[2 * p] - m;
                float t = av + 0.5f * pv - 0.5f * __expf(pv) * dd * dd;
                sum_t[2 * p] += __expf(t);
                sum_a[2 * p] += __expf(av);
            }
            {
                float m = m1 + bm, pv = p1 + bp, av = g1 + ba;
                float dd = xv[2 * p + 1] - m;
                float t = av + 0.5f * pv - 0.5f * __expf(pv) * dd * dd;
                sum_t[2 * p + 1] += __expf(t);
                sum_a[2 * p + 1] += __expf(av);
            }
        }
    }

    float part = 0.0f;
    #pragma unroll
    for (int r = 0; r < ROWS_PB; r++)
        part += __logf(sum_t[r]) - __logf(sum_a[r]);

    __syncthreads();
    part = block_reduce_256(part);
    if (threadIdx.x == 0) g_partC[blockIdx.x] = part;
}

// ---------------------------------------------------------------------------
// Final reduction: out = -( (PB + PC)/N + c2 ),  c2 = -0.5*D*log(2*pi)
// ---------------------------------------------------------------------------
__global__ __launch_bounds__(256) void final_k(float* __restrict__ out)
{
    float s = 0.0f;
    for (int i = threadIdx.x; i < NB_SAMP; i += 256) s += g_partB[i];
    for (int i = threadIdx.x; i < NB_DEC; i += 256) s += g_partC[i];
    s = block_reduce_256(s);
    if (threadIdx.x == 0) {
        const float c2 = -0.5f * 256.0f * 1.8378770664093453f;
        out[0] = -(s / (float)N_ROWS + c2);
    }
}

extern "C" void kernel_launch(void* const* d_in, const int* in_sizes, int n_in,
                              void* d_out, int out_size) {
    const float* x  = (const float*)d_in[0];
    const float* We = (const float*)d_in[1];
    const float* be = (const float*)d_in[2];
    const float* Wd = (const float*)d_in[3];
    const float* bd = (const float*)d_in[4];
    const float* ue = (const float*)d_in[5];
    const float* rr = (const float*)d_in[6];
    float* out = (float*)d_out;

    dim3 ge(ENC_OUT / 64, B_ROWS / 64);
    enc_gemm<<<ge, 256>>>(x, We, be);
    sample_k<<<NB_SAMP, 256>>>(ue, rr);
    dec_k<<<NB_DEC, 256>>>(x, Wd, bd);
    final_k<<<1, 256>>>(out);
}

// round 4
// speedup vs baseline: 1.6733x; 1.1970x over previous
#include <cuda_runtime.h>
#include <cuda_bf16.h>
#include <cstdint>

#define K_COMP   8
#define L_LAT    64
#define D_DATA   256
#define N_ROWS   16384
#define B_ROWS   2048
#define ENC_OUT  1536   // 3*K*L
#define DEC_OUT  6144   // 3*K*D
#define NB_SAMP  4096   // (16384*64)/256
#define ROWS_PB  16
#define NB_DEC   (N_ROWS / ROWS_PB)   // 1024
#define WPK_N    (3 * 32 * 2048)      // 196608 packed words

__device__ float    g_pred_e[B_ROWS * ENC_OUT];   // 12.6 MB
__device__ float    g_h[N_ROWS * L_LAT];          // 4 MB
__device__ uint32_t g_wpk[WPK_N];                 // W_d bf16, l-pairs packed
__device__ float    g_partB[NB_SAMP];
__device__ float    g_partC[NB_DEC];

// ---- packed helpers ------------------------------------------------------
typedef unsigned long long u64;

__device__ __forceinline__ u64 pack2(float lo, float hi) {
    u64 o; asm("mov.b64 %0, {%1, %2};" : "=l"(o) : "f"(lo), "f"(hi)); return o;
}
__device__ __forceinline__ u64 bcast2(float v) {
    u64 o; asm("mov.b64 %0, {%1, %1};" : "=l"(o) : "f"(v)); return o;
}
__device__ __forceinline__ void unpack2(u64 d, float& lo, float& hi) {
    asm("mov.b64 {%0, %1}, %2;" : "=f"(lo), "=f"(hi) : "l"(d));
}
__device__ __forceinline__ void fma2(u64& d, u64 a, u64 b) {
    asm("fma.rn.f32x2 %0, %1, %2, %0;" : "+l"(d) : "l"(a), "l"(b));
}
__device__ __forceinline__ uint32_t bf16x2_pack(float hi, float lo) {
    uint32_t o; asm("cvt.rn.bf16x2.f32 %0, %1, %2;" : "=r"(o) : "f"(hi), "f"(lo)); return o;
}
__device__ __forceinline__ uint32_t hfma2(uint32_t a, uint32_t b, uint32_t c) {
    uint32_t d; asm("fma.rn.bf16x2 %0, %1, %2, %3;" : "=r"(d) : "r"(a), "r"(b), "r"(c));
    return d;
}
__device__ __forceinline__ float bf_lo(uint32_t v) { return __uint_as_float(v << 16); }
__device__ __forceinline__ float bf_hi(uint32_t v) { return __uint_as_float(v & 0xFFFF0000u); }

__device__ __forceinline__ float block_reduce_256(float v) {
    __shared__ float red[8];
    int lane = threadIdx.x & 31, wid = threadIdx.x >> 5;
    #pragma unroll
    for (int o = 16; o > 0; o >>= 1) v += __shfl_down_sync(0xffffffffu, v, o);
    if (lane == 0) red[wid] = v;
    __syncthreads();
    if (wid == 0) {
        v = (lane < 8) ? red[lane] : 0.0f;
        #pragma unroll
        for (int o = 4; o > 0; o >>= 1) v += __shfl_down_sync(0xffffffffu, v, o);
    }
    return v;   // valid on thread 0
}

// ---------------------------------------------------------------------------
// Pack W_d -> bf16 l-pairs: g_wpk[(t*32+l2)*2048 + col] =
//   {bf16(Wd[2*l2+1][t*2048+col]) , bf16(Wd[2*l2][t*2048+col])}
// ---------------------------------------------------------------------------
__global__ __launch_bounds__(256) void prep_w(const float* __restrict__ Wd)
{
    int i = blockIdx.x * 256 + threadIdx.x;   // < 196608
    int col = i & 2047;
    int tl = i >> 11;            // t*32 + l2
    int t = tl >> 5, l2 = tl & 31;
    int base = t * 2048 + col;
    float w0 = Wd[(2 * l2) * DEC_OUT + base];
    float w1 = Wd[(2 * l2 + 1) * DEC_OUT + base];
    g_wpk[i] = bf16x2_pack(w1, w0);
}

// ---------------------------------------------------------------------------
// Encoder GEMM (fp32 FFMA2): pred_e(2048,1536) = x @ W_e + b_e
// ---------------------------------------------------------------------------
__global__ __launch_bounds__(256) void enc_gemm(const float* __restrict__ x,
                                                const float* __restrict__ We,
                                                const float* __restrict__ be)
{
    __shared__ float As[16][64];
    __shared__ float Bs[16][64];
    const int tid = threadIdx.x;
    const int tx = tid & 15, ty = tid >> 4;
    const int bm = blockIdx.y * 64, bn = blockIdx.x * 64;

    u64 acc[4][2];
    #pragma unroll
    for (int i = 0; i < 4; i++) { acc[i][0] = pack2(0.f, 0.f); acc[i][1] = pack2(0.f, 0.f); }

    const int am = tid >> 2;
    const int ak = (tid & 3) * 4;
    const int bk = tid >> 6;
    const int bnn = tid & 63;

    for (int kt = 0; kt < 256; kt += 16) {
        float4 xa = *reinterpret_cast<const float4*>(x + (bm + am) * D_DATA + kt + ak);
        As[ak + 0][am] = xa.x;
        As[ak + 1][am] = xa.y;
        As[ak + 2][am] = xa.z;
        As[ak + 3][am] = xa.w;
        #pragma unroll
        for (int i = 0; i < 4; i++)
            Bs[bk + i * 4][bnn] = We[(kt + bk + i * 4) * ENC_OUT + bn + bnn];
        __syncthreads();

        #pragma unroll
        for (int kk = 0; kk < 16; kk++) {
            float4 av = *reinterpret_cast<const float4*>(&As[kk][ty * 4]);
            u64 b01 = *reinterpret_cast<const u64*>(&Bs[kk][tx * 4]);
            u64 b23 = *reinterpret_cast<const u64*>(&Bs[kk][tx * 4 + 2]);
            u64 a0 = bcast2(av.x), a1 = bcast2(av.y), a2 = bcast2(av.z), a3 = bcast2(av.w);
            fma2(acc[0][0], a0, b01); fma2(acc[0][1], a0, b23);
            fma2(acc[1][0], a1, b01); fma2(acc[1][1], a1, b23);
            fma2(acc[2][0], a2, b01); fma2(acc[2][1], a2, b23);
            fma2(acc[3][0], a3, b01); fma2(acc[3][1], a3, b23);
        }
        __syncthreads();
    }

    #pragma unroll
    for (int i = 0; i < 4; i++) {
        float v0, v1, v2, v3;
        unpack2(acc[i][0], v0, v1);
        unpack2(acc[i][1], v2, v3);
        int col = bn + tx * 4;
        float* outp = g_pred_e + (bm + ty * 4 + i) * ENC_OUT + col;
        outp[0] = v0 + be[col + 0];
        outp[1] = v1 + be[col + 1];
        outp[2] = v2 + be[col + 2];
        outp[3] = v3 + be[col + 3];
    }
}

// ---------------------------------------------------------------------------
// Sampling + h + (L_q - L_e) partials. One thread per (n, l). fp32 exact.
// ---------------------------------------------------------------------------
__global__ __launch_bounds__(256) void sample_k(const float* __restrict__ ue,
                                                const float* __restrict__ rr)
{
    const int g = blockIdx.x * 256 + threadIdx.x;
    const int n = g >> 6, l = g & 63;
    const float* row = g_pred_e + (n & (B_ROWS - 1)) * ENC_OUT;

    float a[K_COMP], e[K_COMP];
    float amax = -1e30f;
    #pragma unroll
    for (int k = 0; k < K_COMP; k++) {
        a[k] = row[1024 + k * 64 + l];
        amax = fmaxf(amax, a[k]);
    }
    float s = 0.0f;
    #pragma unroll
    for (int k = 0; k < K_COMP; k++) { e[k] = __expf(a[k] - amax); s += e[k]; }
    const float lse_a = amax + __logf(s);
    const float inv = 1.0f / s;

    const float rv = rr[n * 64 + l];
    float c = 0.0f;
    int idx = 0;
    #pragma unroll
    for (int k = 0; k < K_COMP; k++) {
        c += e[k] * inv;
        idx += (rv > c) ? 1 : 0;
    }
    if (idx > K_COMP - 1) idx = K_COMP - 1;

    const float msel = row[idx * 64 + l];
    const float psel = row[512 + idx * 64 + l];
    const float hv = msel + __expf(-0.5f * psel) * ue[n * 64 + l];
    g_h[n * 64 + l] = hv;

    float st = 0.0f;
    #pragma unroll
    for (int k = 0; k < K_COMP; k++) {
        float m = row[k * 64 + l];
        float p = row[512 + k * 64 + l];
        float dd = hv - m;
        st += __expf(a[k] + 0.5f * p - 0.5f * __expf(p) * dd * dd);
    }
    const float lse_s = __logf(st) - lse_a;

    float v = -0.5f * hv * hv - lse_s;
    v = block_reduce_256(v);
    if (threadIdx.x == 0) g_partB[blockIdx.x] = v;
}

// ---------------------------------------------------------------------------
// Fused decoder GEMM + mixture likelihood: bf16 HFMA2 (rt=2, no RF-bank hit).
// Block: 256 threads (1 per d-col), 16 rows = 8 bf16x2 row-pairs.
// Per 2-l iter: 3 LDG.32 (packed bf16 w) + 6 PRMT (dup halves) + 16 LDS.32
// (broadcast h pairs) + 48 HFMA2. FMA pipe-bound at 96 cyc/iter.
// ---------------------------------------------------------------------------
__global__ __launch_bounds__(256, 2) void dec_k(const float* __restrict__ x,
                                                const float* __restrict__ bd)
{
    const int d = threadIdx.x;
    const int row0 = blockIdx.x * ROWS_PB;
    __shared__ uint32_t hp[64][8];   // [l][pair] = {bf16 h[2p+1][l], bf16 h[2p][l]}

    for (int i = threadIdx.x; i < 512; i += 256) {
        int l = i >> 3, p = i & 7;
        float h0 = g_h[(row0 + 2 * p) * 64 + l];
        float h1 = g_h[(row0 + 2 * p + 1) * 64 + l];
        hp[l][p] = bf16x2_pack(h1, h0);
    }
    __syncthreads();

    float xv[ROWS_PB];
    const int xrow = row0 & (B_ROWS - 1);
    #pragma unroll
    for (int r = 0; r < ROWS_PB; r++)
        xv[r] = x[(xrow + r) * D_DATA + d];

    float sum_t[ROWS_PB], sum_a[ROWS_PB];
    #pragma unroll
    for (int r = 0; r < ROWS_PB; r++) { sum_t[r] = 0.0f; sum_a[r] = 0.0f; }

    for (int k = 0; k < K_COMP; k++) {
        uint32_t am[8], ap[8], aa[8];
        #pragma unroll
        for (int p = 0; p < 8; p++) { am[p] = 0u; ap[p] = 0u; aa[p] = 0u; }

        const uint32_t* w = g_wpk + k * 256 + d;
        #pragma unroll 4
        for (int l2 = 0; l2 < 32; l2++) {
            uint32_t vm = w[l2 * 2048];
            uint32_t vp = w[32 * 2048 + l2 * 2048];
            uint32_t va = w[64 * 2048 + l2 * 2048];
            uint32_t bm0 = __byte_perm(vm, vm, 0x1010), bm1 = __byte_perm(vm, vm, 0x3232);
            uint32_t bp0 = __byte_perm(vp, vp, 0x1010), bp1 = __byte_perm(vp, vp, 0x3232);
            uint32_t ba0 = __byte_perm(va, va, 0x1010), ba1 = __byte_perm(va, va, 0x3232);
            #pragma unroll
            for (int p = 0; p < 8; p++) {
                uint32_t h0 = hp[2 * l2][p];
                uint32_t h1 = hp[2 * l2 + 1][p];
                am[p] = hfma2(h0, bm0, am[p]);
                ap[p] = hfma2(h0, bp0, ap[p]);
                aa[p] = hfma2(h0, ba0, aa[p]);
                am[p] = hfma2(h1, bm1, am[p]);
                ap[p] = hfma2(h1, bp1, ap[p]);
                aa[p] = hfma2(h1, ba1, aa[p]);
            }
        }

        const float bm = bd[k * D_DATA + d];
        const float bp = bd[2048 + k * D_DATA + d];
        const float ba = bd[4096 + k * D_DATA + d];
        #pragma unroll
        for (int p = 0; p < 8; p++) {
            {
                float m = bf_lo(am[p]) + bm, pv = bf_lo(ap[p]) + bp, av = bf_lo(aa[p]) + ba;
                float dd = xv[2 * p] - m;
                float t = av + 0.5f * pv - 0.5f * __expf(pv) * dd * dd;
                sum_t[2 * p] += __expf(t);
                sum_a[2 * p] += __expf(av);
            }
            {
                float m = bf_hi(am[p]) + bm, pv = bf_hi(ap[p]) + bp, av = bf_hi(aa[p]) + ba;
                float dd = xv[2 * p + 1] - m;
                float t = av + 0.5f * pv - 0.5f * __expf(pv) * dd * dd;
                sum_t[2 * p + 1] += __expf(t);
                sum_a[2 * p + 1] += __expf(av);
            }
        }
    }

    float part = 0.0f;
    #pragma unroll
    for (int r = 0; r < ROWS_PB; r++)
        part += __logf(sum_t[r]) - __logf(sum_a[r]);

    __syncthreads();
    part = block_reduce_256(part);
    if (threadIdx.x == 0) g_partC[blockIdx.x] = part;
}

// ---------------------------------------------------------------------------
// Final reduction: out = -( (PB + PC)/N + c2 ),  c2 = -0.5*D*log(2*pi)
// ---------------------------------------------------------------------------
__global__ __launch_bounds__(256) void final_k(float* __restrict__ out)
{
    float s = 0.0f;
    const float4* pb = reinterpret_cast<const float4*>(g_partB);
    for (int i = threadIdx.x; i < NB_SAMP / 4; i += 256) {
        float4 v = pb[i]; s += (v.x + v.y) + (v.z + v.w);
    }
    const float4* pc = reinterpret_cast<const float4*>(g_partC);
    for (int i = threadIdx.x; i < NB_DEC / 4; i += 256) {
        float4 v = pc[i]; s += (v.x + v.y) + (v.z + v.w);
    }
    s = block_reduce_256(s);
    if (threadIdx.x == 0) {
        const float c2 = -0.5f * 256.0f * 1.8378770664093453f;
        out[0] = -(s / (float)N_ROWS + c2);
    }
}

extern "C" void kernel_launch(void* const* d_in, const int* in_sizes, int n_in,
                              void* d_out, int out_size) {
    const float* x  = (const float*)d_in[0];
    const float* We = (const float*)d_in[1];
    const float* be = (const float*)d_in[2];
    const float* Wd = (const float*)d_in[3];
    const float* bd = (const float*)d_in[4];
    const float* ue = (const float*)d_in[5];
    const float* rr = (const float*)d_in[6];
    float* out = (float*)d_out;

    prep_w<<<WPK_N / 256, 256>>>(Wd);
    dim3 ge(ENC_OUT / 64, B_ROWS / 64);
    enc_gemm<<<ge, 256>>>(x, We, be);
    sample_k<<<NB_SAMP, 256>>>(ue, rr);
    dec_k<<<NB_DEC, 256>>>(x, bd);
    final_k<<<1, 256>>>(out);
}